// round 17
// baseline (speedup 1.0000x reference)
#include <cuda_runtime.h>
#include <cstdint>

#define DIM   768
#define HOUT  64
#define ROWS  128          // rows per CTA (16 per warp, 8 warps)
#define NTH   256
#define KC    32
#define NCH   24           // DIM/KC
#define XS    36           // X smem row stride (words): frag banks (4g+t) distinct
#define VS    68           // V stride (words), conflict-free A-frag reads

// smem words: two X bufs + two 8KB packed-weight bufs = 53,248 B -> 4 CTAs/SM
// V (128 x VS = 8704 words) overlays the X-buffer region after stage 1
#define XBUF0 0
#define XBUF1 (128*XS)             // 4608
#define WBUF0 (2*128*XS)           // 9216
#define WBUF1 (WBUF0 + 2048)       // 11264
#define SMEM_WORDS (WBUF0 + 4096)  // 13312
#define SMEM_BYTES (SMEM_WORDS*4)  // 53248

// fragment-packed tf32 weights (contiguous 8KB per k/n-chunk for cp.async staging)
__device__ __align__(16) uint2 g_wvf[96*8*32];     // [k8][nt0..7][lane]
__device__ __align__(16) uint2 g_wof[24*8*4*32];   // [c32][ks][nt0..3][lane]

__device__ __forceinline__ uint32_t f2tf(float f) {
    uint32_t u;
    asm("cvt.rna.tf32.f32 %0, %1;" : "=r"(u) : "f"(f));
    return u;
}

__device__ __forceinline__ void mma_tf32(float* c, const uint32_t* a, uint32_t b0, uint32_t b1) {
    asm volatile(
        "mma.sync.aligned.m16n8k8.row.col.f32.tf32.tf32.f32 "
        "{%0,%1,%2,%3}, {%4,%5,%6,%7}, {%8,%9}, {%0,%1,%2,%3};\n"
        : "+f"(c[0]), "+f"(c[1]), "+f"(c[2]), "+f"(c[3])
        : "r"(a[0]), "r"(a[1]), "r"(a[2]), "r"(a[3]), "r"(b0), "r"(b1));
}

__device__ __forceinline__ void cpa16(uint32_t dst, const void* src) {
    asm volatile("cp.async.cg.shared.global [%0], [%1], 16;\n" :: "r"(dst), "l"(src));
}
#define CP_COMMIT() asm volatile("cp.async.commit_group;\n")
#define CP_WAIT0()  asm volatile("cp.async.wait_group 0;\n")

// pack Wv/Wo into MMA B-fragment lane order (tf32-rounded) — unchanged from R13
__global__ void prep_weights(const float* __restrict__ Wv, const float* __restrict__ Wo) {
    int i = blockIdx.x * blockDim.x + threadIdx.x;   // 0..24575
    if (i >= 96*8*32) return;
    int lane = i & 31, g = lane >> 2, t = lane & 3;
    {   // g_wvf: k8 = i>>8 (0..95), nt = (i>>5)&7
        int nt = (i >> 5) & 7, k8 = i >> 8;
        int row = nt * 8 + g, k = k8 * 8 + t;
        g_wvf[i] = make_uint2(f2tf(Wv[row * DIM + k]), f2tf(Wv[row * DIM + k + 4]));
    }
    {   // g_wof: c = i>>10 (0..23), ks = (i>>7)&7, nt = (i>>5)&3
        int nt = (i >> 5) & 3, ks = (i >> 7) & 7, c = i >> 10;
        int row = c * 32 + nt * 8 + g, k = ks * 8 + t;
        g_wof[i] = make_uint2(f2tf(Wo[row * HOUT + k]), f2tf(Wo[row * HOUT + k + 4]));
    }
}

// out = (x @ Wv^T + bv) @ Wo^T + bo
// (softmax over the singleton sequence axis in the reference is identically 1,
//  so q/k/scan are mathematically dead)
// 8 warps x 16 rows: halved per-thread registers -> 32 warps/SM at 4 CTAs.
__global__ void __launch_bounds__(NTH, 4)
fused_vo_kernel(const float* __restrict__ x,
                const float* __restrict__ bv,
                const float* __restrict__ bo,
                float* __restrict__ out,
                int nrows)
{
    extern __shared__ uint32_t sm[];
    uint32_t sbase;
    {
        uint64_t tmp;
        asm("cvta.to.shared.u64 %0, %1;" : "=l"(tmp) : "l"(sm));
        sbase = (uint32_t)tmp;
    }

    const int tid   = threadIdx.x;
    const int warp  = tid >> 5;
    const int lane  = tid & 31;
    const int g     = lane >> 2;
    const int t     = lane & 3;
    const int row0  = blockIdx.x * ROWS;
    const int wbase = warp * 16;            // one m16 tile per warp

    float acc[8][4];
#pragma unroll
    for (int nt = 0; nt < 8; nt++)
#pragma unroll
        for (int i = 0; i < 4; i++) acc[nt][i] = 0.f;

    // ================= stage 1: V = X @ Wv^T =================
    auto issue1 = [&](int c) {
        const int xb = (c & 1) ? XBUF1 : XBUF0;
        const int wb = (c & 1) ? WBUF1 : WBUF0;
        // X chunk: 1024 segs(16B), 4/thread, coalesced
#pragma unroll
        for (int p = 0; p < 4; p++) {
            int f = p * NTH + tid;
            int r = f >> 3, s16 = f & 7;
            int gr = row0 + r; if (gr >= nrows) gr = nrows - 1;
            cpa16(sbase + (uint32_t)(xb + r * XS + s16 * 4) * 4,
                  x + (size_t)gr * DIM + c * KC + s16 * 4);
        }
        // packed Wv chunk: contiguous 8KB = 512 segs, 2/thread
        const char* wsrc = (const char*)g_wvf + (size_t)c * 8192;
#pragma unroll
        for (int p = 0; p < 2; p++) {
            int f = p * NTH + tid;
            cpa16(sbase + (uint32_t)(wb + f * 4) * 4, wsrc + (size_t)f * 16);
        }
        CP_COMMIT();
    };

    issue1(0);
#pragma unroll 1
    for (int c = 0; c < NCH; c++) {
        CP_WAIT0();
        __syncthreads();                 // chunk c ready AND buf (c+1)&1 readers done
        if (c < NCH - 1) issue1(c + 1);
        const int xb = (c & 1) ? XBUF1 : XBUF0;
        const uint2* wb = (const uint2*)&sm[(c & 1) ? WBUF1 : WBUF0];
#pragma unroll
        for (int ks = 0; ks < 4; ks++) {
            uint32_t a[4];
            {
                int r = wbase + g;
                a[0] = sm[xb + r * XS + ks * 8 + t];
                a[1] = sm[xb + (r + 8) * XS + ks * 8 + t];
                a[2] = sm[xb + r * XS + ks * 8 + t + 4];
                a[3] = sm[xb + (r + 8) * XS + ks * 8 + t + 4];
            }
#pragma unroll
            for (int nt = 0; nt < 8; nt++) {
                uint2 b = wb[(ks * 8 + nt) * 32 + lane];   // lane-linear LDS.64
                mma_tf32(acc[nt], a, b.x, b.y);
            }
        }
    }

    // start stage-2 weight pipeline early: WBUF0's last reader was compute(22),
    // which every thread finished before the c=23 barrier above.
    auto issue2 = [&](int c) {
        const int wb = (c & 1) ? WBUF1 : WBUF0;
        const char* wsrc = (const char*)g_wof + (size_t)c * 8192;
#pragma unroll
        for (int p = 0; p < 2; p++) {
            int f = p * NTH + tid;
            cpa16(sbase + (uint32_t)(wb + f * 4) * 4, wsrc + (size_t)f * 16);
        }
        CP_COMMIT();
    };
    issue2(0);

    // V overlays the X-buffer region (crosses warp row boundaries) -> one barrier
    __syncthreads();

    // write V (+bv), tf32-rounded; V rows are warp-private for stage-2 reads
#pragma unroll
    for (int nt = 0; nt < 8; nt++) {
        int col = nt * 8 + 2 * t;
        int r   = wbase + g;
        float b0v = __ldg(bv + col);
        float b1v = __ldg(bv + col + 1);
        sm[r * VS + col]           = f2tf(acc[nt][0] + b0v);
        sm[r * VS + col + 1]       = f2tf(acc[nt][1] + b1v);
        sm[(r + 8) * VS + col]     = f2tf(acc[nt][2] + b0v);
        sm[(r + 8) * VS + col + 1] = f2tf(acc[nt][3] + b1v);
    }
    __syncwarp();   // stage-2 V readers are this warp's own lanes

    // ================= stage 2: OUT = V @ Wo^T =================
#pragma unroll 1
    for (int c = 0; c < NCH; c++) {          // 32 output cols per chunk
        CP_WAIT0();
        __syncthreads();
        if (c < NCH - 1) issue2(c + 1);
        const uint2* wb = (const uint2*)&sm[(c & 1) ? WBUF1 : WBUF0];

        float acc2[4][4];
#pragma unroll
        for (int nt = 0; nt < 4; nt++)
#pragma unroll
            for (int i = 0; i < 4; i++) acc2[nt][i] = 0.f;

#pragma unroll
        for (int ks = 0; ks < 8; ks++) {
            uint32_t a[4];
            {
                int r = wbase + g;
                a[0] = sm[r * VS + ks * 8 + t];
                a[1] = sm[(r + 8) * VS + ks * 8 + t];
                a[2] = sm[r * VS + ks * 8 + t + 4];
                a[3] = sm[(r + 8) * VS + ks * 8 + t + 4];
            }
#pragma unroll
            for (int nt = 0; nt < 4; nt++) {
                uint2 b = wb[(ks * 4 + nt) * 32 + lane];
                mma_tf32(acc2[nt], a, b.x, b.y);
            }
        }
        // fused +bo, coalesced float2 stores
        const int n0 = c * 32;
#pragma unroll
        for (int nt = 0; nt < 4; nt++) {
            int col = n0 + nt * 8 + 2 * t;
            float bo0 = __ldg(bo + col);
            float bo1 = __ldg(bo + col + 1);
            int r = row0 + wbase + g;
            if (r < nrows) {
                float2 o = make_float2(acc2[nt][0] + bo0, acc2[nt][1] + bo1);
                *(float2*)(out + (size_t)r * DIM + col) = o;
            }
            if (r + 8 < nrows) {
                float2 o = make_float2(acc2[nt][2] + bo0, acc2[nt][3] + bo1);
                *(float2*)(out + (size_t)(r + 8) * DIM + col) = o;
            }
        }
    }
}

extern "C" void kernel_launch(void* const* d_in, const int* in_sizes, int n_in,
                              void* d_out, int out_size)
{
    // metadata order: x, q_state, Wq, bq, Wk, bk, Wv, bv, Wo, bo
    const float* x  = (const float*)d_in[0];
    const float* Wv = (const float*)d_in[6];
    const float* bv = (const float*)d_in[7];
    const float* Wo = (const float*)d_in[8];
    const float* bo = (const float*)d_in[9];
    float* out = (float*)d_out;

    int nrows = in_sizes[0] / DIM;
    int grid  = (nrows + ROWS - 1) / ROWS;

    prep_weights<<<96, 256>>>(Wv, Wo);

    cudaFuncSetAttribute(fused_vo_kernel,
                         cudaFuncAttributeMaxDynamicSharedMemorySize, SMEM_BYTES);
    fused_vo_kernel<<<grid, NTH, SMEM_BYTES>>>(x, bv, bo, out, nrows);
}